// round 11
// baseline (speedup 1.0000x reference)
#include <cuda_runtime.h>
#include <cuda_bf16.h>
#include <math.h>
#include <stdint.h>

// Problem constants
#define PB 4096     // batch
#define PF 2048     // features
#define PK 64       // concepts
#define PD 8        // box dim
#define PN 1024     // K*2D
#define KD 512      // K*D

// INT8 GEMM tiling
#define IBK 64              // int8 elems per K chunk
#define INK (PF / IBK)      // 32
#define ROWB 80             // smem row stride bytes (64 + 16 pad, ldsm conflict-free)

// Quantization scales (inputs: A ~ N(0,1) max<7; W ~ N(0,1)/sqrt(2048) max<0.15)
#define SA_SCALE (32639.0f / 7.0f)
#define SW_SCALE (32639.0f / 0.15f)

// ---------------- scratch (__device__ globals) ----------------
__device__ __align__(16) signed char g_A1[PB * PF];   // A hi int8 plane [b][f]
__device__ __align__(16) signed char g_A0[PB * PF];   // A lo
__device__ __align__(16) signed char g_W1[PN * PF];   // W^T hi int8 plane [n][f]
__device__ __align__(16) signed char g_W0[PN * PF];   // W^T lo
__device__ float g_theta[PB * PN];                    // GEMM output

// ---------------- PTX helpers ----------------
__device__ __forceinline__ void cpasync16(void* dst, const void* src) {
    uint32_t d = (uint32_t)__cvta_generic_to_shared(dst);
    asm volatile("cp.async.cg.shared.global [%0], [%1], 16;\n" :: "r"(d), "l"(src));
}
__device__ __forceinline__ void ldsm_x4(uint32_t* r, uint32_t addr) {
    asm volatile("ldmatrix.sync.aligned.m8n8.x4.shared.b16 {%0,%1,%2,%3}, [%4];\n"
                 : "=r"(r[0]), "=r"(r[1]), "=r"(r[2]), "=r"(r[3]) : "r"(addr));
}
__device__ __forceinline__ void imma16832(int* c, const uint32_t* a, uint32_t b0, uint32_t b1) {
    asm volatile(
        "mma.sync.aligned.m16n8k32.row.col.s32.s8.s8.s32 "
        "{%0,%1,%2,%3}, {%4,%5,%6,%7}, {%8,%9}, {%0,%1,%2,%3};\n"
        : "+r"(c[0]), "+r"(c[1]), "+r"(c[2]), "+r"(c[3])
        : "r"(a[0]), "r"(a[1]), "r"(a[2]), "r"(a[3]), "r"(b0), "r"(b1));
}
__device__ __forceinline__ float ex2_fast(float x) {
    float r; asm("ex2.approx.ftz.f32 %0, %1;" : "=f"(r) : "f"(x)); return r;
}
__device__ __forceinline__ float lg2_fast(float x) {
    float r; asm("lg2.approx.ftz.f32 %0, %1;" : "=f"(r) : "f"(x)); return r;
}

// int16 -> (hi int8, lo int8) with v = hi*256 + lo, lo in [-128,127]
__device__ __forceinline__ void split16(float x, float scale, signed char& hi, signed char& lo) {
    int q = __float2int_rn(x * scale);
    q = max(-32640, min(32639, q));
    int l8 = (int)((signed char)(q & 0xFF));
    hi = (signed char)((q - l8) >> 8);
    lo = (signed char)l8;
}

// ---------------- kernel: combined quantize+split conversions ----------------
// blocks [0, 8192): A (features), 4 elems/thread
// blocks [8192, 16384): Wp transpose+split -> [n][f], 1 elem/thread
__global__ void cvt_kernel(const float* __restrict__ A, const float* __restrict__ Wp) {
    if (blockIdx.x < 8192) {
        int i = (blockIdx.x * 256 + threadIdx.x) * 4;
        float4 v = *(const float4*)(A + i);
        char4 h, l;
        split16(v.x, SA_SCALE, h.x, l.x);
        split16(v.y, SA_SCALE, h.y, l.y);
        split16(v.z, SA_SCALE, h.z, l.z);
        split16(v.w, SA_SCALE, h.w, l.w);
        *(char4*)(g_A1 + i) = h;
        *(char4*)(g_A0 + i) = l;
    } else {
        int idx = (blockIdx.x - 8192) * 256 + threadIdx.x;   // idx = n*PF + f
        int n = idx >> 11;
        int f = idx & 2047;
        float w = Wp[(n >> 4) * (PF * 16) + f * 16 + (n & 15)];
        signed char hi, lo;
        split16(w, SW_SCALE, hi, lo);
        g_W1[idx] = hi;
        g_W0[idx] = lo;
    }
}

// ---------------- kernel: int8 split tensor-core GEMM ----------------
// theta = A*W^T + bias, via 3 IMMA products: A1*W1 (2^16), A1*W0 + A0*W1 (2^8)
struct ISmem {
    signed char A1[2][128][ROWB];
    signed char A0[2][128][ROWB];
    signed char W1[2][128][ROWB];
    signed char W0[2][128][ROWB];
};  // 81920 bytes

__global__ __launch_bounds__(256) void gemmi_kernel(const float* __restrict__ bias) {
    extern __shared__ char sm_raw[];
    ISmem* sm = (ISmem*)sm_raw;
    const int tid = threadIdx.x;
    const int warp = tid >> 5;
    const int l = tid & 31;
    const int wm = warp >> 2;       // 0..1
    const int wn = warp & 3;        // 0..3
    const int row0 = blockIdx.y * 128;
    const int col0 = blockIdx.x * 128;

    int acc_h[4][4][4];   // P11 tier
    int acc_x[4][4][4];   // P10 + P01 tier
#pragma unroll
    for (int mi = 0; mi < 4; mi++)
#pragma unroll
        for (int ni = 0; ni < 4; ni++)
#pragma unroll
            for (int r = 0; r < 4; r++) { acc_h[mi][ni][r] = 0; acc_x[mi][ni][r] = 0; }

    const signed char* pa1 = g_A1 + (size_t)row0 * PF;
    const signed char* pa0 = g_A0 + (size_t)row0 * PF;
    const signed char* pw1 = g_W1 + (size_t)col0 * PF;
    const signed char* pw0 = g_W0 + (size_t)col0 * PF;

    const int lrow = tid >> 2;          // 0..63
    const int lch  = (tid & 3) * 16;    // 0,16,32,48

    auto load_stage = [&](int kt, int s) {
        int k0 = kt * IBK;
#pragma unroll
        for (int r = 0; r < 2; r++) {
            int rr = lrow + r * 64;
            size_t go = (size_t)rr * PF + k0 + lch;
            cpasync16(&sm->A1[s][rr][lch], pa1 + go);
            cpasync16(&sm->A0[s][rr][lch], pa0 + go);
            cpasync16(&sm->W1[s][rr][lch], pw1 + go);
            cpasync16(&sm->W0[s][rr][lch], pw0 + go);
        }
        asm volatile("cp.async.commit_group;\n");
    };

    load_stage(0, 0);

    const int lr16 = l & 15;
    const int lhalf = (l >> 4) * 16;   // byte offset within 32B k-chunk

    for (int kt = 0; kt < INK; kt++) {
        const int s = kt & 1;
        if (kt + 1 < INK) {
            load_stage(kt + 1, s ^ 1);
            asm volatile("cp.async.wait_group 1;\n");
        } else {
            asm volatile("cp.async.wait_group 0;\n");
        }
        __syncthreads();

#pragma unroll
        for (int ks = 0; ks < 2; ks++) {
            const int koff = ks * 32;
            // B fragments: W planes, [n][k] layout, non-trans x4 = 16 n-rows x 32B
            uint32_t w1f[2][4], w0f[2][4];
#pragma unroll
            for (int h = 0; h < 2; h++) {
                uint32_t ad = (uint32_t)__cvta_generic_to_shared(
                    &sm->W1[s][wn * 32 + h * 16 + lr16][koff + lhalf]);
                ldsm_x4(w1f[h], ad);
                ad = (uint32_t)__cvta_generic_to_shared(
                    &sm->W0[s][wn * 32 + h * 16 + lr16][koff + lhalf]);
                ldsm_x4(w0f[h], ad);
            }
            uint32_t a4[4][4];
            // A1 frags, then P11 + P10
#pragma unroll
            for (int mi = 0; mi < 4; mi++) {
                uint32_t ad = (uint32_t)__cvta_generic_to_shared(
                    &sm->A1[s][wm * 64 + mi * 16 + lr16][koff + lhalf]);
                ldsm_x4(a4[mi], ad);
            }
#pragma unroll
            for (int mi = 0; mi < 4; mi++)
#pragma unroll
                for (int ni = 0; ni < 4; ni++) {
                    int nh = ni >> 1, np = ni & 1;
                    imma16832(acc_h[mi][ni], a4[mi], w1f[nh][np], w1f[nh][np + 2]);
                    imma16832(acc_x[mi][ni], a4[mi], w0f[nh][np], w0f[nh][np + 2]);
                }
            // A0 frags (reuse regs), then P01
#pragma unroll
            for (int mi = 0; mi < 4; mi++) {
                uint32_t ad = (uint32_t)__cvta_generic_to_shared(
                    &sm->A0[s][wm * 64 + mi * 16 + lr16][koff + lhalf]);
                ldsm_x4(a4[mi], ad);
            }
#pragma unroll
            for (int mi = 0; mi < 4; mi++)
#pragma unroll
                for (int ni = 0; ni < 4; ni++) {
                    int nh = ni >> 1, np = ni & 1;
                    imma16832(acc_x[mi][ni], a4[mi], w1f[nh][np], w1f[nh][np + 2]);
                }
        }
        __syncthreads();
    }

    // epilogue: dequantize, add bias, store fp32 theta
    const float C_HI = 65536.0f / (SA_SCALE * SW_SCALE);
    const float C_LO = 256.0f / (SA_SCALE * SW_SCALE);
    const int rbase = row0 + wm * 64 + (l >> 2);
    const int cbase = col0 + wn * 32 + (l & 3) * 2;
#pragma unroll
    for (int mi = 0; mi < 4; mi++) {
#pragma unroll
        for (int ni = 0; ni < 4; ni++) {
            int r = rbase + mi * 16;
            int c = cbase + ni * 8;
            float b0 = bias[c], b1 = bias[c + 1];
            float2 v0;
            v0.x = (float)acc_h[mi][ni][0] * C_HI + (float)acc_x[mi][ni][0] * C_LO + b0;
            v0.y = (float)acc_h[mi][ni][1] * C_HI + (float)acc_x[mi][ni][1] * C_LO + b1;
            *(float2*)(g_theta + (size_t)r * PN + c) = v0;
            float2 v1;
            v1.x = (float)acc_h[mi][ni][2] * C_HI + (float)acc_x[mi][ni][2] * C_LO + b0;
            v1.y = (float)acc_h[mi][ni][3] * C_HI + (float)acc_x[mi][ni][3] * C_LO + b1;
            *(float2*)(g_theta + (size_t)(r + 8) * PN + c) = v1;
        }
    }
}

// fast softplus: ln(1+e^x) with hardware MUFU
__device__ __forceinline__ float softplus_f(float x) {
    float e = __expf(-fabsf(x));
    return fmaxf(x, 0.f) + __logf(1.f + e);
}

// ---------------- fused kernel: per-b prep + pairwise cond + task logit ----------------
__global__ __launch_bounds__(256) void fused_kernel(const float* __restrict__ Wprob,
                                                    const float* __restrict__ bprob,
                                                    const float* __restrict__ Wbox,
                                                    const float* __restrict__ Wrel,
                                                    const float* __restrict__ bbox,
                                                    const float* __restrict__ brel,
                                                    float* __restrict__ out_task,
                                                    float* __restrict__ out_cp,
                                                    float* __restrict__ out_cond) {
    const int b = blockIdx.x;
    const int tid = threadIdx.x;

    __shared__ float s_ez[KD], s_eZ[KD], s_vinv[PK];   // [k][d] layout
    __shared__ float s_cond[PK * PK];
    __shared__ float s_red[8];
    __shared__ float s_bd[2];

    // ---- prep phase: threads 0..63 handle k = tid ----
    if (tid < PK) {
        const int k = tid;
        const float* th = g_theta + (size_t)b * PN + k * 16;
        float4 t0 = *(const float4*)(th);
        float4 t1 = *(const float4*)(th + 4);
        float4 t2 = *(const float4*)(th + 8);
        float4 t3 = *(const float4*)(th + 12);
        float z[PD]  = {t0.x, t0.y, t0.z, t0.w, t1.x, t1.y, t1.z, t1.w};
        float w2[PD] = {t2.x, t2.y, t2.z, t2.w, t3.x, t3.y, t3.z, t3.w};

        float Z[PD], v[PD];
#pragma unroll
        for (int d = 0; d < PD; d++) {
            v[d] = softplus_f(w2[d]);    // Z - z >= 0
            Z[d] = z[d] + v[d];
        }

        const float* wp = Wprob + k * 16;
        float logit = bprob[k];
#pragma unroll
        for (int d = 0; d < PD; d++) logit += z[d] * wp[d] + Z[d] * wp[8 + d];
        float p = 1.f / (1.f + __expf(-logit));
        out_cp[b * PK + k] = p;

        const float* wb = Wbox + k * 16;
        float bd = 0.f;
#pragma unroll
        for (int d = 0; d < PD; d++) bd += z[d] * wb[d] + Z[d] * wb[8 + d];
        bd *= p;

        const float C10 = 14.426950408889634f;  // 10/ln2
        float ez[PD], eZ[PD];
        float vprod = 1.f;
#pragma unroll
        for (int d = 0; d < PD; d++) {
            ez[d] = ex2_fast(z[d] * C10);
            eZ[d] = ex2_fast(-Z[d] * C10);
            float sp2 = 2.f * v[d] + __logf(1.f + __expf(-2.f * v[d]));  // softplus(2v)
            vprod *= sp2;
        }
        *(float4*)(s_ez + k * PD)     = make_float4(ez[0], ez[1], ez[2], ez[3]);
        *(float4*)(s_ez + k * PD + 4) = make_float4(ez[4], ez[5], ez[6], ez[7]);
        *(float4*)(s_eZ + k * PD)     = make_float4(eZ[0], eZ[1], eZ[2], eZ[3]);
        *(float4*)(s_eZ + k * PD + 4) = make_float4(eZ[4], eZ[5], eZ[6], eZ[7]);
        s_vinv[k] = 1.f / vprod;

        float s = bd;
#pragma unroll
        for (int off = 16; off; off >>= 1) s += __shfl_down_sync(0xffffffffu, s, off);
        if ((k & 31) == 0) s_bd[k >> 5] = s;
    }
    __syncthreads();

    // ---- pairwise phase: symmetric half-pairs ----
    const int i = tid & 63;
    const int g = tid >> 6;
    float ezi[PD], eZi[PD];
    {
        float4 a0 = *(const float4*)(s_ez + i * PD);
        float4 a1 = *(const float4*)(s_ez + i * PD + 4);
        float4 c0 = *(const float4*)(s_eZ + i * PD);
        float4 c1 = *(const float4*)(s_eZ + i * PD + 4);
        ezi[0]=a0.x; ezi[1]=a0.y; ezi[2]=a0.z; ezi[3]=a0.w;
        ezi[4]=a1.x; ezi[5]=a1.y; ezi[6]=a1.z; ezi[7]=a1.w;
        eZi[0]=c0.x; eZi[1]=c0.y; eZi[2]=c0.z; eZi[3]=c0.w;
        eZi[4]=c1.x; eZi[5]=c1.y; eZi[6]=c1.z; eZi[7]=c1.w;
    }
    const float vinv_i = s_vinv[i];

    const float CLO = 1e-6f;
    const float CHI = 1.0f - 1e-6f;
    const float LN2P8 = 0.05328484f;   // ln(2)^8

    const int qmax = (g == 0) ? 9 : 8;
    for (int q = 0; q < qmax; q++) {
        const int off = g + 4 * q;
        const int j = (i + off) & 63;
        float4 e0 = *(const float4*)(s_ez + j * PD);
        float4 e1 = *(const float4*)(s_ez + j * PD + 4);
        float4 f0 = *(const float4*)(s_eZ + j * PD);
        float4 f1 = *(const float4*)(s_eZ + j * PD + 4);
        float ezj[PD] = {e0.x, e0.y, e0.z, e0.w, e1.x, e1.y, e1.z, e1.w};
        float eZj[PD] = {f0.x, f0.y, f0.z, f0.w, f1.x, f1.y, f1.z, f1.w};
        float prod = LN2P8;
#pragma unroll
        for (int d = 0; d < PD; d++) {
            float S = ezi[d] + ezj[d];
            float T = eZi[d] + eZj[d];
            float m = lg2_fast(S * T);
            float e = ex2_fast(-0.2f * m);     // (S*T)^{-1/5} = exp(2u)
            prod *= lg2_fast(1.f + e);         // log2-domain softplus(2u)
        }
        float ci = fminf(fmaxf(prod * s_vinv[j], CLO), CHI);  // cond(i,j)
        float cj = fminf(fmaxf(prod * vinv_i,   CLO), CHI);   // cond(j,i)
        s_cond[i * PK + j] = ci;
        s_cond[j * PK + i] = cj;
    }
    __syncthreads();

    // coalesced writeout + fused Wrel dot
    float relsum = 0.f;
    float* outp = out_cond + (size_t)b * (PK * PK);
#pragma unroll
    for (int r = 0; r < 4; r++) {
        int idx = (tid + r * 256) * 4;
        float4 c = *(const float4*)(s_cond + idx);
        float4 w = *(const float4*)(Wrel + idx);
        relsum += c.x * w.x + c.y * w.y + c.z * w.z + c.w * w.w;
        *(float4*)(outp + idx) = c;
    }

#pragma unroll
    for (int off = 16; off; off >>= 1) relsum += __shfl_down_sync(0xffffffffu, relsum, off);
    if ((tid & 31) == 0) s_red[tid >> 5] = relsum;
    __syncthreads();
    if (tid == 0) {
        float tot = 0.f;
#pragma unroll
        for (int w = 0; w < 8; w++) tot += s_red[w];
        tot += s_bd[0] + s_bd[1] + bbox[0] + brel[0];
        out_task[b] = 1.f / (1.f + __expf(-tot));
    }
}

// ---------------- launch ----------------
extern "C" void kernel_launch(void* const* d_in, const int* in_sizes, int n_in,
                              void* d_out, int out_size) {
    const float* features = (const float*)d_in[0];  // (B,F)
    const float* Wp       = (const float*)d_in[1];  // (K,F,2D)
    const float* bp       = (const float*)d_in[2];  // (K,2D)
    const float* Wprob    = (const float*)d_in[3];  // (K,2D)
    const float* bprob    = (const float*)d_in[4];  // (K,)
    const float* Wbox     = (const float*)d_in[5];  // (K*2D,1)
    const float* bbox     = (const float*)d_in[6];  // (1,)
    const float* Wrel     = (const float*)d_in[7];  // (K*K,1)
    const float* brel     = (const float*)d_in[8];  // (1,)

    float* out = (float*)d_out;
    float* out_task = out;                      // [B]
    float* out_cp   = out + PB;                 // [B,K]
    float* out_cond = out + PB + PB * PK;       // [B,K,K]

    // 0. quantize + split conversions
    cvt_kernel<<<16384, 256>>>(features, Wp);

    // 1. int8 split tensor-core GEMM
    int smem_bytes = (int)sizeof(ISmem);
    cudaFuncSetAttribute(gemmi_kernel, cudaFuncAttributeMaxDynamicSharedMemorySize, smem_bytes);
    dim3 ggrid(PN / 128, PB / 128);   // (8, 32)
    gemmi_kernel<<<ggrid, 256, smem_bytes>>>(bp);

    // 2. fused prep + pairwise + task logit
    fused_kernel<<<PB, 256>>>(Wprob, bprob, Wbox, Wrel, bbox, brel,
                              out_task, out_cp, out_cond);
}

// round 13
// speedup vs baseline: 5.9236x; 5.9236x over previous
#include <cuda_runtime.h>
#include <cuda_fp16.h>
#include <math.h>
#include <stdint.h>

// Problem constants
#define PB 4096     // batch
#define PF 2048     // features
#define PK 64       // concepts
#define PD 8        // box dim
#define PN 1024     // K*2D
#define KD 512      // K*D

// GEMM tiling
#define BM 128
#define BN 128
#define BK 32
#define APAD 8
#define BPAD 8
#define NK (PF / BK)   // 64

// ---------------- scratch (__device__ globals) ----------------
__device__ __half g_Ah[PB * PF];     // features fp16 [b][f]
__device__ __half g_Wh[PF * PN];     // transposed weights fp16 [f][n]
__device__ float g_theta[PB * PN];   // GEMM output

// ---------------- PTX helpers ----------------
__device__ __forceinline__ void cpasync16(void* dst, const void* src) {
    uint32_t d = (uint32_t)__cvta_generic_to_shared(dst);
    asm volatile("cp.async.cg.shared.global [%0], [%1], 16;\n" :: "r"(d), "l"(src));
}
__device__ __forceinline__ void ldsm_x4(uint32_t* r, uint32_t addr) {
    asm volatile("ldmatrix.sync.aligned.m8n8.x4.shared.b16 {%0,%1,%2,%3}, [%4];\n"
                 : "=r"(r[0]), "=r"(r[1]), "=r"(r[2]), "=r"(r[3]) : "r"(addr));
}
__device__ __forceinline__ void ldsm_x4t(uint32_t* r, uint32_t addr) {
    asm volatile("ldmatrix.sync.aligned.m8n8.x4.trans.shared.b16 {%0,%1,%2,%3}, [%4];\n"
                 : "=r"(r[0]), "=r"(r[1]), "=r"(r[2]), "=r"(r[3]) : "r"(addr));
}
__device__ __forceinline__ void mma16816h(float* c, const uint32_t* a, uint32_t b0, uint32_t b1) {
    asm volatile(
        "mma.sync.aligned.m16n8k16.row.col.f32.f16.f16.f32 "
        "{%0,%1,%2,%3}, {%4,%5,%6,%7}, {%8,%9}, {%0,%1,%2,%3};\n"
        : "+f"(c[0]), "+f"(c[1]), "+f"(c[2]), "+f"(c[3])
        : "r"(a[0]), "r"(a[1]), "r"(a[2]), "r"(a[3]), "r"(b0), "r"(b1));
}
__device__ __forceinline__ float ex2_fast(float x) {
    float r; asm("ex2.approx.ftz.f32 %0, %1;" : "=f"(r) : "f"(x)); return r;
}
__device__ __forceinline__ float lg2_fast(float x) {
    float r; asm("lg2.approx.ftz.f32 %0, %1;" : "=f"(r) : "f"(x)); return r;
}

// ---------------- kernel: combined conversions (fp32 -> fp16) ----------------
// blocks [0, 8192): A (features), 4 elems/thread
// blocks [8192, 16384): Wp transpose -> [f][n], 1 elem/thread
__global__ void cvt_kernel(const float* __restrict__ A, const float* __restrict__ Wp) {
    if (blockIdx.x < 8192) {
        int i = (blockIdx.x * 256 + threadIdx.x) * 4;
        float4 v = *(const float4*)(A + i);
        __half2 h01 = __floats2half2_rn(v.x, v.y);
        __half2 h23 = __floats2half2_rn(v.z, v.w);
        *(__half2*)(g_Ah + i)     = h01;
        *(__half2*)(g_Ah + i + 2) = h23;
    } else {
        int idx = (blockIdx.x - 8192) * 256 + threadIdx.x;   // idx = f*1024 + n
        int f = idx >> 10;
        int n = idx & 1023;
        g_Wh[idx] = __float2half_rn(Wp[(n >> 4) * (PF * 16) + f * 16 + (n & 15)]);
    }
}

// ---------------- kernel: fp16 tensor-core GEMM ----------------
struct SmemT {
    __half A[2][BM][BK + APAD];
    __half B[2][BK][BN + BPAD];
};

__global__ __launch_bounds__(256, 2) void gemmh_kernel(const float* __restrict__ bias) {
    extern __shared__ char sm_raw[];
    SmemT* sm = (SmemT*)sm_raw;
    const int tid = threadIdx.x;
    const int warp = tid >> 5;
    const int l = tid & 31;
    const int wm = warp >> 2;       // 0..1
    const int wn = warp & 3;        // 0..3
    const int row0 = blockIdx.y * BM;
    const int col0 = blockIdx.x * BN;

    float acc[4][4][4];
#pragma unroll
    for (int mi = 0; mi < 4; mi++)
#pragma unroll
        for (int ni = 0; ni < 4; ni++)
#pragma unroll
            for (int r = 0; r < 4; r++) acc[mi][ni][r] = 0.f;

    const __half* Ap = g_Ah + (size_t)row0 * PF;
    const __half* Bp = g_Wh + col0;

    const int arow = tid >> 2;          // 0..63
    const int acol = (tid & 3) * 8;     // 0,8,16,24
    const int brow = tid >> 4;          // 0..15
    const int bcol = (tid & 15) * 8;    // 0..120

    auto load_stage = [&](int kt, int s) {
        int k0 = kt * BK;
        const __half* ah = Ap + k0;
#pragma unroll
        for (int r = 0; r < 2; r++) {
            int row = arow + r * 64;
            cpasync16(&sm->A[s][row][acol], ah + (size_t)row * PF + acol);
        }
        const __half* bh = Bp + (size_t)k0 * PN;
#pragma unroll
        for (int r = 0; r < 2; r++) {
            int row = brow + r * 16;
            cpasync16(&sm->B[s][row][bcol], bh + (size_t)row * PN + bcol);
        }
        asm volatile("cp.async.commit_group;\n");
    };

    load_stage(0, 0);

    const int lr16 = l & 15;
    const int lhalf = (l >> 4) * 8;

    for (int kt = 0; kt < NK; kt++) {
        const int s = kt & 1;
        if (kt + 1 < NK) {
            load_stage(kt + 1, s ^ 1);
            asm volatile("cp.async.wait_group 1;\n");
        } else {
            asm volatile("cp.async.wait_group 0;\n");
        }
        __syncthreads();

#pragma unroll
        for (int ks = 0; ks < 2; ks++) {
            const int kk = ks * 16;
            uint32_t a4[4][4], b4[2][4];
            // B fragments: x4 trans = 2 n-blocks (16 cols) per instruction
#pragma unroll
            for (int np = 0; np < 2; np++) {
                int nc = wn * 32 + np * 16 + lhalf;
                uint32_t addr = (uint32_t)__cvta_generic_to_shared(&sm->B[s][kk + lr16][nc]);
                ldsm_x4t(b4[np], addr);
            }
#pragma unroll
            for (int mi = 0; mi < 4; mi++) {
                int mrow = wm * 64 + mi * 16 + lr16;
                uint32_t addr = (uint32_t)__cvta_generic_to_shared(&sm->A[s][mrow][kk + lhalf]);
                ldsm_x4(a4[mi], addr);
            }
#pragma unroll
            for (int mi = 0; mi < 4; mi++)
#pragma unroll
                for (int ni = 0; ni < 4; ni++)
                    mma16816h(acc[mi][ni], a4[mi], b4[ni >> 1][(ni & 1) * 2],
                              b4[ni >> 1][(ni & 1) * 2 + 1]);
        }
        __syncthreads();
    }

    // epilogue: add bias, store fp32 theta
    const int rbase = row0 + wm * 64 + (l >> 2);
    const int cbase = col0 + wn * 32 + (l & 3) * 2;
#pragma unroll
    for (int mi = 0; mi < 4; mi++) {
#pragma unroll
        for (int ni = 0; ni < 4; ni++) {
            int r = rbase + mi * 16;
            int c = cbase + ni * 8;
            float b0 = bias[c], b1 = bias[c + 1];
            float2 v0; v0.x = acc[mi][ni][0] + b0; v0.y = acc[mi][ni][1] + b1;
            *(float2*)(g_theta + (size_t)r * PN + c) = v0;
            float2 v1; v1.x = acc[mi][ni][2] + b0; v1.y = acc[mi][ni][3] + b1;
            *(float2*)(g_theta + (size_t)(r + 8) * PN + c) = v1;
        }
    }
}

// fast softplus: ln(1+e^x) with hardware MUFU
__device__ __forceinline__ float softplus_f(float x) {
    float e = __expf(-fabsf(x));
    return fmaxf(x, 0.f) + __logf(1.f + e);
}

// ---------------- fused kernel: per-b prep + pairwise cond + task logit ----------------
// Transposed smem tables: s_ez[d*64+k] (bank-conflict-free for strided j access)
__global__ __launch_bounds__(256) void fused_kernel(const float* __restrict__ Wprob,
                                                    const float* __restrict__ bprob,
                                                    const float* __restrict__ Wbox,
                                                    const float* __restrict__ Wrel,
                                                    const float* __restrict__ bbox,
                                                    const float* __restrict__ brel,
                                                    float* __restrict__ out_task,
                                                    float* __restrict__ out_cp,
                                                    float* __restrict__ out_cond) {
    const int b = blockIdx.x;
    const int tid = threadIdx.x;

    __shared__ float s_ez[KD], s_eZ[KD], s_vinv[PK];   // [d][k] layout
    __shared__ float s_cond[PK * PK];
    __shared__ float s_red[8];
    __shared__ float s_bd[2];

    // ---- prep phase: threads 0..63 handle k = tid ----
    if (tid < PK) {
        const int k = tid;
        const float* th = g_theta + (size_t)b * PN + k * 16;
        float4 t0 = *(const float4*)(th);
        float4 t1 = *(const float4*)(th + 4);
        float4 t2 = *(const float4*)(th + 8);
        float4 t3 = *(const float4*)(th + 12);
        float z[PD]  = {t0.x, t0.y, t0.z, t0.w, t1.x, t1.y, t1.z, t1.w};
        float w2[PD] = {t2.x, t2.y, t2.z, t2.w, t3.x, t3.y, t3.z, t3.w};

        float Z[PD], v[PD];
#pragma unroll
        for (int d = 0; d < PD; d++) {
            v[d] = softplus_f(w2[d]);    // Z - z >= 0
            Z[d] = z[d] + v[d];
        }

        // concept logit -> prob
        const float* wp = Wprob + k * 16;
        float logit = bprob[k];
#pragma unroll
        for (int d = 0; d < PD; d++) logit += z[d] * wp[d] + Z[d] * wp[8 + d];
        float p = 1.f / (1.f + __expf(-logit));
        out_cp[b * PK + k] = p;

        // box-dot partial: p * (z . Wbox[k][0:8] + Z . Wbox[k][8:16])
        const float* wb = Wbox + k * 16;
        float bd = 0.f;
#pragma unroll
        for (int d = 0; d < PD; d++) bd += z[d] * wb[d] + Z[d] * wb[8 + d];
        bd *= p;

        // exp tables (transposed smem) + scalar inverse box volume
        const float C10 = 14.426950408889634f;  // 10/ln2
        float vprod = 1.f;
#pragma unroll
        for (int d = 0; d < PD; d++) {
            s_ez[d * PK + k] = ex2_fast(z[d] * C10);
            s_eZ[d * PK + k] = ex2_fast(-Z[d] * C10);
            float sp2 = 2.f * v[d] + __logf(1.f + __expf(-2.f * v[d]));  // softplus(2v)
            vprod *= sp2;
        }
        s_vinv[k] = 1.f / vprod;

        // reduce bd within each of the 2 warps
        float s = bd;
#pragma unroll
        for (int off = 16; off; off >>= 1) s += __shfl_down_sync(0xffffffffu, s, off);
        if ((k & 31) == 0) s_bd[k >> 5] = s;
    }
    __syncthreads();

    // ---- pairwise phase: symmetric half-pairs ----
    const int i = tid & 63;
    const int g = tid >> 6;
    float ezi[PD], eZi[PD];
#pragma unroll
    for (int d = 0; d < PD; d++) {
        ezi[d] = s_ez[d * PK + i];
        eZi[d] = s_eZ[d * PK + i];
    }
    const float vinv_i = s_vinv[i];

    const float CLO = 1e-6f;
    const float CHI = 1.0f - 1e-6f;
    const float LN2P8 = 0.05328484f;   // ln(2)^8

    const int qmax = (g == 0) ? 9 : 8;
    for (int q = 0; q < qmax; q++) {
        const int off = g + 4 * q;
        const int j = (i + off) & 63;
        float prod = LN2P8;
#pragma unroll
        for (int d = 0; d < PD; d++) {
            float S = ezi[d] + s_ez[d * PK + j];
            float T = eZi[d] + s_eZ[d * PK + j];
            float m = lg2_fast(S * T);
            float e = ex2_fast(-0.2f * m);     // (S*T)^{-1/5} = exp(2u)
            prod *= lg2_fast(1.f + e);         // log2-domain softplus(2u)
        }
        float ci = fminf(fmaxf(prod * s_vinv[j], CLO), CHI);  // cond(i,j)
        float cj = fminf(fmaxf(prod * vinv_i,   CLO), CHI);   // cond(j,i)
        s_cond[i * PK + j] = ci;
        s_cond[j * PK + i] = cj;
    }
    __syncthreads();

    // coalesced writeout + fused Wrel dot
    float relsum = 0.f;
    float* outp = out_cond + (size_t)b * (PK * PK);
#pragma unroll
    for (int r = 0; r < 4; r++) {
        int idx = (tid + r * 256) * 4;
        float4 c = *(const float4*)(s_cond + idx);
        float4 w = *(const float4*)(Wrel + idx);
        relsum += c.x * w.x + c.y * w.y + c.z * w.z + c.w * w.w;
        *(float4*)(outp + idx) = c;
    }

#pragma unroll
    for (int off = 16; off; off >>= 1) relsum += __shfl_down_sync(0xffffffffu, relsum, off);
    if ((tid & 31) == 0) s_red[tid >> 5] = relsum;
    __syncthreads();
    if (tid == 0) {
        float tot = 0.f;
#pragma unroll
        for (int w = 0; w < 8; w++) tot += s_red[w];
        tot += s_bd[0] + s_bd[1] + bbox[0] + brel[0];
        out_task[b] = 1.f / (1.f + __expf(-tot));
    }
}

// ---------------- launch ----------------
extern "C" void kernel_launch(void* const* d_in, const int* in_sizes, int n_in,
                              void* d_out, int out_size) {
    const float* features = (const float*)d_in[0];  // (B,F)
    const float* Wp       = (const float*)d_in[1];  // (K,F,2D)
    const float* bp       = (const float*)d_in[2];  // (K,2D)
    const float* Wprob    = (const float*)d_in[3];  // (K,2D)
    const float* bprob    = (const float*)d_in[4];  // (K,)
    const float* Wbox     = (const float*)d_in[5];  // (K*2D,1)
    const float* bbox     = (const float*)d_in[6];  // (1,)
    const float* Wrel     = (const float*)d_in[7];  // (K*K,1)
    const float* brel     = (const float*)d_in[8];  // (1,)

    float* out = (float*)d_out;
    float* out_task = out;                      // [B]
    float* out_cp   = out + PB;                 // [B,K]
    float* out_cond = out + PB + PB * PK;       // [B,K,K]

    // 0. combined conversions (fp32 -> fp16)
    cvt_kernel<<<16384, 256>>>(features, Wp);

    // 1. single fp16 tensor-core GEMM
    int smem_bytes = (int)sizeof(SmemT);
    cudaFuncSetAttribute(gemmh_kernel, cudaFuncAttributeMaxDynamicSharedMemorySize, smem_bytes);
    dim3 ggrid(PN / BN, PB / BM);   // (8, 32)
    gemmh_kernel<<<ggrid, 256, smem_bytes>>>(bp);

    // 2. fused prep + pairwise + task logit
    fused_kernel<<<PB, 256>>>(Wprob, bprob, Wbox, Wrel, bbox, brel,
                              out_task, out_cp, out_cond);
}